// round 4
// baseline (speedup 1.0000x reference)
#include <cuda_runtime.h>
#include <cuda_bf16.h>

#define G_MAX 128
#define BLOCK 128
#define IPT   4

__global__ __launch_bounds__(BLOCK)
void roi_match_kernel(const float4* __restrict__ props,
                      const float4* __restrict__ gt,
                      const int*    __restrict__ gtl32,   // gt labels, i32 or i64 (auto-detect)
                      float*        __restrict__ out_labels,
                      float4*       __restrict__ out_boxes,
                      int N, int G)
{
    __shared__ float4 s_gt[G_MAX];
    __shared__ float  s_area[G_MAX];
    __shared__ float  s_lab[G_MAX];

    const int t = threadIdx.x;
    if (t < G) {
        float4 b = gt[t];
        s_gt[t]   = b;
        s_area[t] = __fmul_rn(__fsub_rn(b.z, b.x), __fsub_rn(b.w, b.y));
        // int64 detection: labels >= 1, so little-endian i64 => word 1 (hi of elem 0) == 0.
        int is64 = (gtl32[1] == 0) ? 1 : 0;
        s_lab[t] = (float)gtl32[is64 ? (2 * t) : t];
    }
    __syncthreads();

    const int base = blockIdx.x * (BLOCK * IPT) + t;

    float4 p[IPT];
    float  parea[IPT], bestI[IPT], bestS[IPT];
    int    bestIdx[IPT], nn[IPT];

    #pragma unroll
    for (int i = 0; i < IPT; ++i) {
        nn[i] = base + i * BLOCK;
        int idx = (nn[i] < N) ? nn[i] : (N - 1);   // clamp tail loads; stores guarded below
        p[i] = props[idx];
        parea[i] = __fmul_rn(__fsub_rn(p[i].z, p[i].x), __fsub_rn(p[i].w, p[i].y));
        // Sentinel best: bestI=0, bestS=1 => first comparison reduces to (inter > 0),
        // and an all-zero row yields iou = 0/1-0 = 0, idx 0 -> label -1, box gt[0],
        // matching jnp.argmax-of-zeros semantics.
        bestI[i] = 0.0f;
        bestS[i] = 1.0f;
        bestIdx[i] = 0;
    }

    #pragma unroll 4
    for (int g = 0; g < G; ++g) {
        const float4 gb = s_gt[g];
        const float  ag = s_area[g];
        #pragma unroll
        for (int i = 0; i < IPT; ++i) {
            float x1 = fmaxf(gb.x, p[i].x);
            float y1 = fmaxf(gb.y, p[i].y);
            float x2 = fminf(gb.z, p[i].z);
            float y2 = fminf(gb.w, p[i].w);
            float dx = fmaxf(__fsub_rn(x2, x1), 0.0f);
            float dy = fmaxf(__fsub_rn(y2, y1), 0.0f);
            float inter = __fmul_rn(dx, dy);
            float S     = __fadd_rn(ag, parea[i]);   // area_g + parea (pre-subtraction sum)
            // iou = inter/(S-inter) is monotone in inter/S (S > 0, inter >= 0):
            //   i1/(S1-i1) > i2/(S2-i2)  <=>  i1*S2 > i2*S1   (cross terms cancel)
            // Division- and subtraction-free argmax; strict > keeps first max,
            // matching jnp.argmax tie semantics. __fmul_rn blocks FMA contraction
            // so the decision rounding is stable.
            bool take = __fmul_rn(inter, bestS[i]) > __fmul_rn(bestI[i], S);
            bestI[i]   = take ? inter : bestI[i];
            bestS[i]   = take ? S     : bestS[i];
            bestIdx[i] = take ? g     : bestIdx[i];
        }
    }

    #pragma unroll
    for (int i = 0; i < IPT; ++i) {
        if (nn[i] < N) {
            // uni = fl(bestS - bestI) reproduces the reference's
            // fl(fl(area1+area2) - inter); single IEEE division -> bitwise-equal iou.
            float uni = __fsub_rn(bestS[i], bestI[i]);
            float iou = __fdiv_rn(bestI[i], uni);
            float lab = s_lab[bestIdx[i]];
            if (iou < 0.5f) lab = (iou >= 0.1f) ? 0.0f : -1.0f;
            if (out_labels) out_labels[nn[i]] = lab;
            if (out_boxes)  out_boxes[nn[i]]  = s_gt[bestIdx[i]];
        }
    }
}

extern "C" void kernel_launch(void* const* d_in, const int* in_sizes, int n_in,
                              void* d_out, int out_size)
{
    const float4* props = (const float4*)d_in[0];
    const float4* gt    = (const float4*)d_in[1];
    const int*    gtl   = (const int*)d_in[2];

    const int N = in_sizes[0] / 4;
    const int G = in_sizes[1] / 4;

    float*  out       = (float*)d_out;
    float*  out_label = nullptr;
    float4* out_boxes = nullptr;

    if (out_size == 5 * N) {            // [labels (N) ; boxes (4N)] as f32
        out_label = out;
        out_boxes = (float4*)(out + N); // 16B-aligned since N % 4 == 0
    } else if (out_size == 4 * N) {     // boxes only
        out_boxes = (float4*)out;
    } else {                            // labels only
        out_label = out;
    }

    const int per_block = BLOCK * IPT;
    const int grid = (N + per_block - 1) / per_block;
    roi_match_kernel<<<grid, BLOCK>>>(props, gt, gtl, out_label, out_boxes, N, G);
}

// round 5
// speedup vs baseline: 1.0904x; 1.0904x over previous
#include <cuda_runtime.h>
#include <cuda_bf16.h>

#define G_MAX 128
#define BLOCK 256

// Lane pairs (2k, 2k+1) share one proposal: even lane scans g in [0, G/2),
// odd lane scans [G/2, G), then they merge with one shfl + exact compare.
__global__ __launch_bounds__(BLOCK)
void roi_match_kernel(const float4* __restrict__ props,
                      const float4* __restrict__ gt,
                      const int*    __restrict__ gtl32,   // gt labels, i32 or i64 (auto-detect)
                      float*        __restrict__ out_labels,
                      float4*       __restrict__ out_boxes,
                      int N, int G)
{
    __shared__ float4 s_gt[G_MAX];
    __shared__ float  s_area[G_MAX];
    __shared__ float  s_lab[G_MAX];

    const int t = threadIdx.x;
    if (t < G) {
        float4 b = gt[t];
        s_gt[t]   = b;
        s_area[t] = __fmul_rn(__fsub_rn(b.z, b.x), __fsub_rn(b.w, b.y));
        // labels >= 1, so little-endian i64 => word 1 (hi word of elem 0) == 0
        int is64 = (gtl32[1] == 0) ? 1 : 0;
        s_lab[t] = (float)gtl32[is64 ? (2 * t) : t];
    }
    __syncthreads();

    const int half = t & 1;
    const int n    = blockIdx.x * (BLOCK / 2) + (t >> 1);
    const int ni   = (n < N) ? n : (N - 1);          // clamp tail loads; stores guarded

    const float4 p = props[ni];
    const float parea = __fmul_rn(__fsub_rn(p.z, p.x), __fsub_rn(p.w, p.y));

    // Sentinel (bestI=0, bestS=1): first comparison reduces to inter > 0.
    // All-zero half keeps idx = gs; merge rules below resolve to global idx 0,
    // matching jnp.argmax-of-zeros.
    float bestI = 0.0f, bestS = 1.0f;
    const int gs = half * (G >> 1);
    const int ge = gs + (G >> 1);
    int bestIdx = gs;

    #pragma unroll 8
    for (int g = gs; g < ge; ++g) {
        const float4 gb = s_gt[g];
        float x1 = fmaxf(gb.x, p.x);
        float y1 = fmaxf(gb.y, p.y);
        float x2 = fminf(gb.z, p.z);
        float y2 = fminf(gb.w, p.w);
        float dx = fmaxf(__fsub_rn(x2, x1), 0.0f);
        float dy = fmaxf(__fsub_rn(y2, y1), 0.0f);
        float inter = __fmul_rn(dx, dy);
        float S     = __fadd_rn(s_area[g], parea);    // area_g + parea
        // iou = inter/(S - inter) monotone in inter/S (S > 0):
        //   i1/(S1-i1) > i2/(S2-i2)  <=>  i1*S2 > i2*S1  (cross terms cancel).
        // FFMA gives the sign of the exact cross-difference to ~1 ulp;
        // d <= 0 keeps the earlier index (jnp.argmax first-max semantics).
        float d = __fmaf_rn(inter, bestS, -__fmul_rn(bestI, S));
        bool take = d > 0.0f;
        bestI   = take ? inter : bestI;
        bestS   = take ? S     : bestS;
        bestIdx = take ? g     : bestIdx;
    }

    // Pair merge: exchange with partner lane, take partner only if strictly
    // greater. On the even lane "mine" holds the smaller g range, so ties
    // (d == 0, e.g. both halves all-zero) keep the smaller index. Only the
    // even lane's merged result is stored.
    float oI   = __shfl_xor_sync(0xffffffffu, bestI, 1);
    float oS   = __shfl_xor_sync(0xffffffffu, bestS, 1);
    int   oIdx = __shfl_xor_sync(0xffffffffu, bestIdx, 1);
    float dm = __fmaf_rn(oI, bestS, -__fmul_rn(bestI, oS));
    if (dm > 0.0f) { bestI = oI; bestS = oS; bestIdx = oIdx; }

    if (half == 0 && n < N) {
        // uni = fl(bestS - bestI) == reference's fl(fl(a1+a2) - inter);
        // single IEEE division -> bitwise-equal iou for the winning pair.
        float uni = __fsub_rn(bestS, bestI);
        float iou = __fdiv_rn(bestI, uni);
        float lab = s_lab[bestIdx];
        if (iou < 0.5f) lab = (iou >= 0.1f) ? 0.0f : -1.0f;
        if (out_labels) out_labels[n] = lab;
        if (out_boxes)  out_boxes[n]  = s_gt[bestIdx];
    }
}

extern "C" void kernel_launch(void* const* d_in, const int* in_sizes, int n_in,
                              void* d_out, int out_size)
{
    const float4* props = (const float4*)d_in[0];
    const float4* gt    = (const float4*)d_in[1];
    const int*    gtl   = (const int*)d_in[2];

    const int N = in_sizes[0] / 4;
    const int G = in_sizes[1] / 4;

    float*  out       = (float*)d_out;
    float*  out_label = nullptr;
    float4* out_boxes = nullptr;

    if (out_size == 5 * N) {            // [labels (N) ; boxes (4N)] as f32
        out_label = out;
        out_boxes = (float4*)(out + N); // 16B-aligned since N % 4 == 0
    } else if (out_size == 4 * N) {     // boxes only
        out_boxes = (float4*)out;
    } else {                            // labels only
        out_label = out;
    }

    const int props_per_block = BLOCK / 2;
    const int grid = (N + props_per_block - 1) / props_per_block;
    roi_match_kernel<<<grid, BLOCK>>>(props, gt, gtl, out_label, out_boxes, N, G);
}